// round 2
// baseline (speedup 1.0000x reference)
#include <cuda_runtime.h>

#define N_NODES 50000
#define N_EDGES 1600000
#define ND 16
#define ED 16
#define HID 64

// Scratch (static device arrays are allowed; cudaMalloc is not)
__device__ float g_xa[N_NODES * HID];   // x @ W1[0:16] + b1   (dst part)
__device__ float g_xb[N_NODES * HID];   // x @ W1[16:32]       (src part)
__device__ float g_agg[N_NODES * ED];   // scatter-sum of e_new
__device__ int   g_idx64;               // 1 if edge_index is int64, 0 if int32

// ---------------------------------------------------------------------------
// packed fp32 FMA (2 MACs/instr on sm_100+); scalar fallback elsewhere
// ---------------------------------------------------------------------------
__device__ __forceinline__ float2 ffma2(float2 a, float2 b, float2 c) {
#if defined(__CUDA_ARCH__) && (__CUDA_ARCH__ >= 1000)
    float2 d;
    asm("fma.rn.f32x2 %0, %1, %2, %3;"
        : "=l"(*reinterpret_cast<unsigned long long*>(&d))
        : "l"(*reinterpret_cast<const unsigned long long*>(&a)),
          "l"(*reinterpret_cast<const unsigned long long*>(&b)),
          "l"(*reinterpret_cast<const unsigned long long*>(&c)));
    return d;
#else
    return make_float2(fmaf(a.x, b.x, c.x), fmaf(a.y, b.y, c.y));
#endif
}

// ---------------------------------------------------------------------------
// Detect edge_index dtype: int64 values must all be in [0, N_NODES).
// If the buffer actually holds int32 data, int64-reinterpreted entries pack
// two random ints -> virtually certainly out of range.
// ---------------------------------------------------------------------------
__global__ void detect_idx_kernel(const void* __restrict__ ei) {
    const long long* p = (const long long*)ei;
    int ok64 = 1;
    for (int i = 0; i < 256; i++) {
        long long v = p[i];
        if (v < 0 || v >= (long long)N_NODES) { ok64 = 0; break; }
    }
    g_idx64 = ok64;
}

// ---------------------------------------------------------------------------
// Kernel A: per-node precompute xa = x@W1a + b1, xb = x@W1b; zero g_agg.
// One block (64 threads) per node.
// ---------------------------------------------------------------------------
__global__ void pre_kernel(const float* __restrict__ x,
                           const float* __restrict__ fR_W1,
                           const float* __restrict__ fR_b1) {
    __shared__ float sx[ND];
    int n = blockIdx.x;
    int j = threadIdx.x;  // 0..63
    if (j < ND) {
        sx[j] = x[n * ND + j];
        g_agg[n * ED + j] = 0.0f;
    }
    __syncthreads();
    float a = fR_b1[j];
    float b = 0.0f;
#pragma unroll
    for (int k = 0; k < ND; k++) {
        float xv = sx[k];
        a = fmaf(xv, fR_W1[k * HID + j], a);
        b = fmaf(xv, fR_W1[(ND + k) * HID + j], b);
    }
    g_xa[n * HID + j] = a;
    g_xb[n * HID + j] = b;
}

// ---------------------------------------------------------------------------
// Kernel B: one thread per edge.
//   h = relu(xa[dst] + xb[src] + e@W1c)      (W1c = fR_W1 rows 32..47)
//   e_new = h @ W2 + b2
//   store e_new; atomicAdd into g_agg[dst]
// ---------------------------------------------------------------------------
__global__ __launch_bounds__(256)
void edge_kernel(const float* __restrict__ e,
                 const void* __restrict__ ei,
                 const float* __restrict__ fR_W1,
                 const float* __restrict__ fR_W2,
                 const float* __restrict__ fR_b2,
                 float* __restrict__ e_new_out) {
    __shared__ __align__(16) float sW1c[ED * HID];   // 16x64
    __shared__ __align__(16) float sW2[HID * ED];    // 64x16
    __shared__ __align__(16) float sb2[ED];

    // cooperative weight load
    for (int i = threadIdx.x; i < ED * HID; i += blockDim.x)
        sW1c[i] = fR_W1[(2 * ND) * HID + i];
    for (int i = threadIdx.x; i < HID * ED; i += blockDim.x)
        sW2[i] = fR_W2[i];
    if (threadIdx.x < ED) sb2[threadIdx.x] = fR_b2[threadIdx.x];
    __syncthreads();

    int eid = blockIdx.x * blockDim.x + threadIdx.x;
    if (eid >= N_EDGES) return;

    long long src, dst;
    if (g_idx64) {
        const long long* p = (const long long*)ei;
        src = p[eid];
        dst = p[N_EDGES + eid];
    } else {
        const int* p = (const int*)ei;
        src = p[eid];
        dst = p[N_EDGES + eid];
    }

    // h init: xa[dst] + xb[src]  (both fit in L2; 12.8MB each)
    float2 h[HID / 2];
    {
        const float4* xa4 = (const float4*)(g_xa + (size_t)dst * HID);
        const float4* xb4 = (const float4*)(g_xb + (size_t)src * HID);
#pragma unroll
        for (int i = 0; i < HID / 4; i++) {
            float4 a = xa4[i];
            float4 b = xb4[i];
            h[2 * i]     = make_float2(a.x + b.x, a.y + b.y);
            h[2 * i + 1] = make_float2(a.z + b.z, a.w + b.w);
        }
    }

    // e row
    float er[ED];
    {
        const float4* e4 = (const float4*)(e + (size_t)eid * ED);
#pragma unroll
        for (int i = 0; i < ED / 4; i++) {
            float4 v = e4[i];
            er[4 * i + 0] = v.x; er[4 * i + 1] = v.y;
            er[4 * i + 2] = v.z; er[4 * i + 3] = v.w;
        }
    }

    // h += e @ W1c   (weights broadcast from shared)
    const float2* w1c2 = (const float2*)sW1c;
#pragma unroll
    for (int k = 0; k < ED; k++) {
        float2 ek = make_float2(er[k], er[k]);
#pragma unroll
        for (int j = 0; j < HID / 2; j++)
            h[j] = ffma2(ek, w1c2[k * (HID / 2) + j], h[j]);
    }

    // relu
#pragma unroll
    for (int j = 0; j < HID / 2; j++) {
        h[j].x = fmaxf(h[j].x, 0.0f);
        h[j].y = fmaxf(h[j].y, 0.0f);
    }

    // out = h @ W2 + b2
    float2 o[ED / 2];
    {
        const float2* sb22 = (const float2*)sb2;
#pragma unroll
        for (int t = 0; t < ED / 2; t++) o[t] = sb22[t];
    }
    const float2* w22 = (const float2*)sW2;
    const float* hs = (const float*)h;
#pragma unroll
    for (int j = 0; j < HID; j++) {
        float2 hj = make_float2(hs[j], hs[j]);
#pragma unroll
        for (int t = 0; t < ED / 2; t++)
            o[t] = ffma2(hj, w22[j * (ED / 2) + t], o[t]);
    }

    // store e_new
    {
        float4* eo = (float4*)(e_new_out + (size_t)eid * ED);
        const float4* o4 = (const float4*)o;
#pragma unroll
        for (int i = 0; i < ED / 4; i++) eo[i] = o4[i];
    }

    // scatter-sum into destination node
    float* ag = g_agg + (size_t)dst * ED;
    const float* os = (const float*)o;
#pragma unroll
    for (int t = 0; t < ED; t++) atomicAdd(ag + t, os[t]);
}

// ---------------------------------------------------------------------------
// Kernel C: per-node fO MLP: x_new = fO(concat(x, agg))
// One thread per node.
// ---------------------------------------------------------------------------
__global__ __launch_bounds__(128)
void node_kernel(const float* __restrict__ x,
                 const float* __restrict__ fO_W1,
                 const float* __restrict__ fO_b1,
                 const float* __restrict__ fO_W2,
                 const float* __restrict__ fO_b2,
                 float* __restrict__ x_new_out) {
    __shared__ __align__(16) float sW1[2 * ND * HID];  // 32x64
    __shared__ __align__(16) float sb1[HID];
    __shared__ __align__(16) float sW2[HID * ND];      // 64x16
    __shared__ __align__(16) float sb2[ND];

    for (int i = threadIdx.x; i < 2 * ND * HID; i += blockDim.x) sW1[i] = fO_W1[i];
    for (int i = threadIdx.x; i < HID * ND; i += blockDim.x) sW2[i] = fO_W2[i];
    if (threadIdx.x < HID) sb1[threadIdx.x] = fO_b1[threadIdx.x];
    if (threadIdx.x < ND) sb2[threadIdx.x] = fO_b2[threadIdx.x];
    __syncthreads();

    int n = blockIdx.x * blockDim.x + threadIdx.x;
    if (n >= N_NODES) return;

    float in[2 * ND];
    {
        const float4* x4 = (const float4*)(x + (size_t)n * ND);
        const float4* a4 = (const float4*)(g_agg + (size_t)n * ED);
#pragma unroll
        for (int i = 0; i < ND / 4; i++) {
            float4 v = x4[i];
            in[4 * i + 0] = v.x; in[4 * i + 1] = v.y;
            in[4 * i + 2] = v.z; in[4 * i + 3] = v.w;
        }
#pragma unroll
        for (int i = 0; i < ED / 4; i++) {
            float4 v = a4[i];
            in[ND + 4 * i + 0] = v.x; in[ND + 4 * i + 1] = v.y;
            in[ND + 4 * i + 2] = v.z; in[ND + 4 * i + 3] = v.w;
        }
    }

    float2 h[HID / 2];
    {
        const float2* sb12 = (const float2*)sb1;
#pragma unroll
        for (int j = 0; j < HID / 2; j++) h[j] = sb12[j];
    }
    const float2* w12 = (const float2*)sW1;
#pragma unroll
    for (int k = 0; k < 2 * ND; k++) {
        float2 ik = make_float2(in[k], in[k]);
#pragma unroll
        for (int j = 0; j < HID / 2; j++)
            h[j] = ffma2(ik, w12[k * (HID / 2) + j], h[j]);
    }
#pragma unroll
    for (int j = 0; j < HID / 2; j++) {
        h[j].x = fmaxf(h[j].x, 0.0f);
        h[j].y = fmaxf(h[j].y, 0.0f);
    }

    float2 o[ND / 2];
    {
        const float2* sb22 = (const float2*)sb2;
#pragma unroll
        for (int t = 0; t < ND / 2; t++) o[t] = sb22[t];
    }
    const float2* w22 = (const float2*)sW2;
    const float* hs = (const float*)h;
#pragma unroll
    for (int j = 0; j < HID; j++) {
        float2 hj = make_float2(hs[j], hs[j]);
#pragma unroll
        for (int t = 0; t < ND / 2; t++)
            o[t] = ffma2(hj, w22[j * (ND / 2) + t], o[t]);
    }

    float4* xo = (float4*)(x_new_out + (size_t)n * ND);
    const float4* o4 = (const float4*)o;
#pragma unroll
    for (int i = 0; i < ND / 4; i++) xo[i] = o4[i];
}

// ---------------------------------------------------------------------------
// kernel_launch
// Inputs: 0:x 1:edge_index 2:e 3:fR_W1 4:fR_b1 5:fR_W2 6:fR_b2
//         7:fO_W1 8:fO_b1 9:fO_W2 10:fO_b2
// Output: [x_new (50000*16) | e_new (1600000*16)] float32
// ---------------------------------------------------------------------------
extern "C" void kernel_launch(void* const* d_in, const int* in_sizes, int n_in,
                              void* d_out, int out_size) {
    const float* x      = (const float*)d_in[0];
    const void*  ei     = d_in[1];
    const float* e      = (const float*)d_in[2];
    const float* fR_W1  = (const float*)d_in[3];
    const float* fR_b1  = (const float*)d_in[4];
    const float* fR_W2  = (const float*)d_in[5];
    const float* fR_b2  = (const float*)d_in[6];
    const float* fO_W1  = (const float*)d_in[7];
    const float* fO_b1  = (const float*)d_in[8];
    const float* fO_W2  = (const float*)d_in[9];
    const float* fO_b2  = (const float*)d_in[10];

    float* x_new = (float*)d_out;
    float* e_new = (float*)d_out + (size_t)N_NODES * ND;

    detect_idx_kernel<<<1, 1>>>(ei);
    pre_kernel<<<N_NODES, HID>>>(x, fR_W1, fR_b1);
    edge_kernel<<<(N_EDGES + 255) / 256, 256>>>(e, ei, fR_W1, fR_W2, fR_b2, e_new);
    node_kernel<<<(N_NODES + 127) / 128, 128>>>(x, fO_W1, fO_b1, fO_W2, fO_b2, x_new);
}

// round 3
// speedup vs baseline: 1.4996x; 1.4996x over previous
#include <cuda_runtime.h>

#define N_NODES 50000
#define N_EDGES 1600000
#define ND 16
#define ED 16
#define HID 64

#define EPB 128            // edges per block (== threads per block)
#define HPAD 68            // padded h row stride in floats (bank-conflict-free)

// Scratch (static device arrays allowed; cudaMalloc is not)
__device__ float g_xa[N_NODES * HID];   // x @ W1[0:16] + b1   (dst part)
__device__ float g_xb[N_NODES * HID];   // x @ W1[16:32]       (src part)
__device__ float g_agg[N_NODES * ED];   // scatter-sum of e_new
__device__ int   g_idx64;               // 1 if edge_index is int64, 0 if int32

// ---------------------------------------------------------------------------
// packed fp32 FMA (2 MACs/instr on sm_100+); scalar fallback elsewhere
// ---------------------------------------------------------------------------
__device__ __forceinline__ float2 ffma2(float2 a, float2 b, float2 c) {
#if defined(__CUDA_ARCH__) && (__CUDA_ARCH__ >= 1000)
    float2 d;
    asm("fma.rn.f32x2 %0, %1, %2, %3;"
        : "=l"(*reinterpret_cast<unsigned long long*>(&d))
        : "l"(*reinterpret_cast<const unsigned long long*>(&a)),
          "l"(*reinterpret_cast<const unsigned long long*>(&b)),
          "l"(*reinterpret_cast<const unsigned long long*>(&c)));
    return d;
#else
    return make_float2(fmaf(a.x, b.x, c.x), fmaf(a.y, b.y, c.y));
#endif
}

// vector reduction to global (sm_90+): one 16B L2 op instead of 4 scalars
__device__ __forceinline__ void red_add_v4(float* p, float4 v) {
#if defined(__CUDA_ARCH__) && (__CUDA_ARCH__ >= 900)
    asm volatile("red.global.add.v4.f32 [%0], {%1,%2,%3,%4};"
                 :: "l"(p), "f"(v.x), "f"(v.y), "f"(v.z), "f"(v.w) : "memory");
#else
    atomicAdd(p + 0, v.x); atomicAdd(p + 1, v.y);
    atomicAdd(p + 2, v.z); atomicAdd(p + 3, v.w);
#endif
}

// ---------------------------------------------------------------------------
// Detect edge_index dtype (int64 vs int32): int64 values must all lie in
// [0, N_NODES); reinterpreted int32 data virtually certainly violates this.
// ---------------------------------------------------------------------------
__global__ void detect_idx_kernel(const void* __restrict__ ei) {
    const long long* p = (const long long*)ei;
    int ok64 = 1;
    for (int i = 0; i < 256; i++) {
        long long v = p[i];
        if (v < 0 || v >= (long long)N_NODES) { ok64 = 0; break; }
    }
    g_idx64 = ok64;
}

// ---------------------------------------------------------------------------
// Kernel A: per-node precompute xa = x@W1a + b1, xb = x@W1b; zero g_agg.
// ---------------------------------------------------------------------------
__global__ void pre_kernel(const float* __restrict__ x,
                           const float* __restrict__ fR_W1,
                           const float* __restrict__ fR_b1) {
    __shared__ float sx[ND];
    int n = blockIdx.x;
    int j = threadIdx.x;  // 0..63
    if (j < ND) {
        sx[j] = x[n * ND + j];
        g_agg[n * ED + j] = 0.0f;
    }
    __syncthreads();
    float a = fR_b1[j];
    float b = 0.0f;
#pragma unroll
    for (int k = 0; k < ND; k++) {
        float xv = sx[k];
        a = fmaf(xv, fR_W1[k * HID + j], a);
        b = fmaf(xv, fR_W1[(ND + k) * HID + j], b);
    }
    g_xa[n * HID + j] = a;
    g_xb[n * HID + j] = b;
}

// ---------------------------------------------------------------------------
// Kernel B (edge): two-stage per block of EPB edges.
//  Stage 1: warp-cooperative coalesced gather: h0 = xa[dst] + xb[src] -> smem
//  Stage 2: one thread per edge: h = relu(h0 + e@W1c); e_new = h@W2 + b2;
//           store e_new; red.v4 into g_agg[dst]
// ---------------------------------------------------------------------------
__global__ __launch_bounds__(EPB, 4)
void edge_kernel(const float* __restrict__ e,
                 const void* __restrict__ ei,
                 const float* __restrict__ fR_W1,
                 const float* __restrict__ fR_W2,
                 const float* __restrict__ fR_b2,
                 float* __restrict__ e_new_out) {
    __shared__ __align__(16) float sW1c[ED * HID];     // 16x64   (4KB)
    __shared__ __align__(16) float sW2[HID * ED];      // 64x16   (4KB)
    __shared__ __align__(16) float sb2[ED];
    __shared__ __align__(16) float sh[EPB * HPAD];     // staged h0 (34KB)

    const int tid  = threadIdx.x;
    const int lane = tid & 31;
    const int wid  = tid >> 5;
    const int base = blockIdx.x * EPB;

    // cooperative weight load
    for (int i = tid; i < ED * HID; i += EPB)
        sW1c[i] = fR_W1[(2 * ND) * HID + i];
    for (int i = tid; i < HID * ED; i += EPB)
        sW2[i] = fR_W2[i];
    if (tid < ED) sb2[tid] = fR_b2[tid];

    // ---- load this thread's edge indices (coalesced) ----
    int src_t, dst_t;
    if (g_idx64) {
        const long long* p = (const long long*)ei;
        src_t = (int)p[base + tid];
        dst_t = (int)p[N_EDGES + base + tid];
    } else {
        const int* p = (const int*)ei;
        src_t = p[base + tid];
        dst_t = p[N_EDGES + base + tid];
    }

    // ---- Stage 1: each warp gathers rows for its own 32 edges ----
    // lane covers an 8B slice of the 256B row; 2 wavefronts per row.
    {
        const int erow0 = wid * 32;  // this warp's first edge (block-local)
#pragma unroll
        for (int i = 0; i < 32; i++) {
            int s = __shfl_sync(0xffffffffu, src_t, i);
            int d = __shfl_sync(0xffffffffu, dst_t, i);
            float2 a = *(const float2*)(g_xa + (size_t)d * HID + 2 * lane);
            float2 b = *(const float2*)(g_xb + (size_t)s * HID + 2 * lane);
            float2 hv = make_float2(a.x + b.x, a.y + b.y);
            *(float2*)(sh + (erow0 + i) * HPAD + 2 * lane) = hv;
        }
    }
    __syncthreads();

    // ---- Stage 2: one thread per edge ----
    const int eid = base + tid;

    // e row (coalesced-ish: 64B stride between lanes)
    float er[ED];
    {
        const float4* e4 = (const float4*)(e + (size_t)eid * ED);
#pragma unroll
        for (int i = 0; i < ED / 4; i++) {
            float4 v = e4[i];
            er[4 * i + 0] = v.x; er[4 * i + 1] = v.y;
            er[4 * i + 2] = v.z; er[4 * i + 3] = v.w;
        }
    }

    // h init from staged smem (conflict-free: stride 68 floats, 4-phase)
    float2 h[HID / 2];
    {
        const float* hr = sh + tid * HPAD;
#pragma unroll
        for (int i = 0; i < HID / 4; i++) {
            float4 v = *(const float4*)(hr + 4 * i);
            h[2 * i]     = make_float2(v.x, v.y);
            h[2 * i + 1] = make_float2(v.z, v.w);
        }
    }

    // h += e @ W1c   (float4 broadcast weights from shared)
    const float4* w1c4 = (const float4*)sW1c;
#pragma unroll
    for (int k = 0; k < ED; k++) {
        float2 ek = make_float2(er[k], er[k]);
#pragma unroll
        for (int j = 0; j < HID / 4; j++) {
            float4 w = w1c4[k * (HID / 4) + j];
            h[2 * j]     = ffma2(ek, make_float2(w.x, w.y), h[2 * j]);
            h[2 * j + 1] = ffma2(ek, make_float2(w.z, w.w), h[2 * j + 1]);
        }
    }

    // relu
#pragma unroll
    for (int j = 0; j < HID / 2; j++) {
        h[j].x = fmaxf(h[j].x, 0.0f);
        h[j].y = fmaxf(h[j].y, 0.0f);
    }

    // out = h @ W2 + b2  (float4 broadcast weights)
    float2 o[ED / 2];
    {
        const float2* sb22 = (const float2*)sb2;
#pragma unroll
        for (int t = 0; t < ED / 2; t++) o[t] = sb22[t];
    }
    const float4* w24 = (const float4*)sW2;
    const float* hs = (const float*)h;
#pragma unroll
    for (int j = 0; j < HID; j++) {
        float2 hj = make_float2(hs[j], hs[j]);
#pragma unroll
        for (int t = 0; t < ED / 4; t++) {
            float4 w = w24[j * (ED / 4) + t];
            o[2 * t]     = ffma2(hj, make_float2(w.x, w.y), o[2 * t]);
            o[2 * t + 1] = ffma2(hj, make_float2(w.z, w.w), o[2 * t + 1]);
        }
    }

    // store e_new
    {
        float4* eo = (float4*)(e_new_out + (size_t)eid * ED);
        const float4* o4 = (const float4*)o;
#pragma unroll
        for (int i = 0; i < ED / 4; i++) eo[i] = o4[i];
    }

    // scatter-sum into destination node (4x fewer L2 ops via v4 reductions)
    {
        float* ag = g_agg + (size_t)dst_t * ED;
        const float4* o4 = (const float4*)o;
#pragma unroll
        for (int i = 0; i < ED / 4; i++) red_add_v4(ag + 4 * i, o4[i]);
    }
}

// ---------------------------------------------------------------------------
// Kernel C: per-node fO MLP: x_new = fO(concat(x, agg)). One thread per node.
// ---------------------------------------------------------------------------
__global__ __launch_bounds__(128)
void node_kernel(const float* __restrict__ x,
                 const float* __restrict__ fO_W1,
                 const float* __restrict__ fO_b1,
                 const float* __restrict__ fO_W2,
                 const float* __restrict__ fO_b2,
                 float* __restrict__ x_new_out) {
    __shared__ __align__(16) float sW1[2 * ND * HID];  // 32x64
    __shared__ __align__(16) float sb1[HID];
    __shared__ __align__(16) float sW2[HID * ND];      // 64x16
    __shared__ __align__(16) float sb2[ND];

    for (int i = threadIdx.x; i < 2 * ND * HID; i += blockDim.x) sW1[i] = fO_W1[i];
    for (int i = threadIdx.x; i < HID * ND; i += blockDim.x) sW2[i] = fO_W2[i];
    if (threadIdx.x < HID) sb1[threadIdx.x] = fO_b1[threadIdx.x];
    if (threadIdx.x < ND) sb2[threadIdx.x] = fO_b2[threadIdx.x];
    __syncthreads();

    int n = blockIdx.x * blockDim.x + threadIdx.x;
    if (n >= N_NODES) return;

    float in[2 * ND];
    {
        const float4* x4 = (const float4*)(x + (size_t)n * ND);
        const float4* a4 = (const float4*)(g_agg + (size_t)n * ED);
#pragma unroll
        for (int i = 0; i < ND / 4; i++) {
            float4 v = x4[i];
            in[4 * i + 0] = v.x; in[4 * i + 1] = v.y;
            in[4 * i + 2] = v.z; in[4 * i + 3] = v.w;
        }
#pragma unroll
        for (int i = 0; i < ED / 4; i++) {
            float4 v = a4[i];
            in[ND + 4 * i + 0] = v.x; in[ND + 4 * i + 1] = v.y;
            in[ND + 4 * i + 2] = v.z; in[ND + 4 * i + 3] = v.w;
        }
    }

    float2 h[HID / 2];
    {
        const float2* sb12 = (const float2*)sb1;
#pragma unroll
        for (int j = 0; j < HID / 2; j++) h[j] = sb12[j];
    }
    const float4* w14 = (const float4*)sW1;
#pragma unroll
    for (int k = 0; k < 2 * ND; k++) {
        float2 ik = make_float2(in[k], in[k]);
#pragma unroll
        for (int j = 0; j < HID / 4; j++) {
            float4 w = w14[k * (HID / 4) + j];
            h[2 * j]     = ffma2(ik, make_float2(w.x, w.y), h[2 * j]);
            h[2 * j + 1] = ffma2(ik, make_float2(w.z, w.w), h[2 * j + 1]);
        }
    }
#pragma unroll
    for (int j = 0; j < HID / 2; j++) {
        h[j].x = fmaxf(h[j].x, 0.0f);
        h[j].y = fmaxf(h[j].y, 0.0f);
    }

    float2 o[ND / 2];
    {
        const float2* sb22 = (const float2*)sb2;
#pragma unroll
        for (int t = 0; t < ND / 2; t++) o[t] = sb22[t];
    }
    const float4* w24 = (const float4*)sW2;
    const float* hs = (const float*)h;
#pragma unroll
    for (int j = 0; j < HID; j++) {
        float2 hj = make_float2(hs[j], hs[j]);
#pragma unroll
        for (int t = 0; t < ND / 4; t++) {
            float4 w = w24[j * (ND / 4) + t];
            o[2 * t]     = ffma2(hj, make_float2(w.x, w.y), o[2 * t]);
            o[2 * t + 1] = ffma2(hj, make_float2(w.z, w.w), o[2 * t + 1]);
        }
    }

    float4* xo = (float4*)(x_new_out + (size_t)n * ND);
    const float4* o4 = (const float4*)o;
#pragma unroll
    for (int i = 0; i < ND / 4; i++) xo[i] = o4[i];
}

// ---------------------------------------------------------------------------
// kernel_launch
// Inputs: 0:x 1:edge_index 2:e 3:fR_W1 4:fR_b1 5:fR_W2 6:fR_b2
//         7:fO_W1 8:fO_b1 9:fO_W2 10:fO_b2
// Output: [x_new (50000*16) | e_new (1600000*16)] float32
// ---------------------------------------------------------------------------
extern "C" void kernel_launch(void* const* d_in, const int* in_sizes, int n_in,
                              void* d_out, int out_size) {
    const float* x      = (const float*)d_in[0];
    const void*  ei     = d_in[1];
    const float* e      = (const float*)d_in[2];
    const float* fR_W1  = (const float*)d_in[3];
    const float* fR_b1  = (const float*)d_in[4];
    const float* fR_W2  = (const float*)d_in[5];
    const float* fR_b2  = (const float*)d_in[6];
    const float* fO_W1  = (const float*)d_in[7];
    const float* fO_b1  = (const float*)d_in[8];
    const float* fO_W2  = (const float*)d_in[9];
    const float* fO_b2  = (const float*)d_in[10];

    float* x_new = (float*)d_out;
    float* e_new = (float*)d_out + (size_t)N_NODES * ND;

    detect_idx_kernel<<<1, 1>>>(ei);
    pre_kernel<<<N_NODES, HID>>>(x, fR_W1, fR_b1);
    edge_kernel<<<N_EDGES / EPB, EPB>>>(e, ei, fR_W1, fR_W2, fR_b2, e_new);
    node_kernel<<<(N_NODES + 127) / 128, 128>>>(x, fO_W1, fO_b1, fO_W2, fO_b2, x_new);
}